// round 14
// baseline (speedup 1.0000x reference)
#include <cuda_runtime.h>
#include <cuda_bf16.h>
#include <math.h>

#define NN   50000
#define EE   800000
#define GG   8
#define HIDD 256
#define RHH  128
#define NEXP 4
#define OUTD 6

// ---------------- scratch (static device globals; no allocation) ----------------
__device__ float g_h   [(size_t)NN * HIDD];
__device__ float g_sw  [(size_t)NN * NEXP];
__device__ float g_small[64];

// CSR by dst
__device__ int g_deg   [NN];
__device__ int g_start [NN + 1];
__device__ int g_cursor[NN];
__device__ int g_csrc  [EE];

// router tie-fixup list
__device__ int g_nflag;
__device__ int g_flag[NN];

// shared split planes
__device__ __nv_bfloat16 g_p0h[(size_t)NN * HIDD];  // aggh hi
__device__ __nv_bfloat16 g_p0l[(size_t)NN * HIDD];  // aggh lo
__device__ __nv_bfloat16 g_p1h[(size_t)NN * HIDD];  // h hi
__device__ __nv_bfloat16 g_p1l[(size_t)NN * HIDD];  // h lo
// per-expert buffers
__device__ __nv_bfloat16 g_xeh[(size_t)NEXP * NN * HIDD];  // xe hi
__device__ __nv_bfloat16 g_xel[(size_t)NEXP * NN * HIDD];  // xe lo
__device__ __nv_bfloat16 g_agh[(size_t)NEXP * NN * HIDD];  // agg hi
__device__ __nv_bfloat16 g_agl[(size_t)NEXP * NN * HIDD];  // agg lo
__device__ float g_xe2f[(size_t)NEXP * NN * HIDD];         // xe2 fp32
// projected outputs: [N][4 experts][8 cols]
__device__ float g_vbuf[(size_t)NN * 32];
__device__ float g_ubuf[(size_t)NN * 32];
// transposed split weights: slot = e*2+l for w_rel, 8+e*2+l for w_root; [slot][n][k]
__device__ __nv_bfloat16 g_wth[16 * 65536];
__device__ __nv_bfloat16 g_wtl[16 * 65536];

// ---------------- utility ----------------
__global__ void zero_kernel(float* __restrict__ p, int n) {
    int i = (blockIdx.x * blockDim.x + threadIdx.x) * 4;
    if (i + 3 < n) {
        *(float4*)(p + i) = make_float4(0.f, 0.f, 0.f, 0.f);
    } else {
        for (int j = i; j < n; ++j) p[j] = 0.f;
    }
}

__global__ void zero_nflag_kernel() {
    if (threadIdx.x == 0) g_nflag = 0;
}

// ---------------- graph stats ----------------
__global__ void count_nodes_kernel(const int* __restrict__ batch) {
    __shared__ float c[GG];
    if (threadIdx.x < GG) c[threadIdx.x] = 0.f;
    __syncthreads();
    int i = blockIdx.x * blockDim.x + threadIdx.x;
    if (i < NN) atomicAdd(&c[batch[i]], 1.0f);
    __syncthreads();
    if (threadIdx.x < GG && c[threadIdx.x] != 0.f)
        atomicAdd(&g_small[threadIdx.x], c[threadIdx.x]);
}

__global__ void count_edges_kernel(const int* __restrict__ src, const int* __restrict__ batch) {
    __shared__ float c[GG];
    if (threadIdx.x < GG) c[threadIdx.x] = 0.f;
    __syncthreads();
    int i = blockIdx.x * blockDim.x + threadIdx.x;
    if (i < EE) atomicAdd(&c[batch[src[i]]], 1.0f);
    __syncthreads();
    if (threadIdx.x < GG && c[threadIdx.x] != 0.f)
        atomicAdd(&g_small[GG + threadIdx.x], c[threadIdx.x]);
}

__global__ void stats_finalize_kernel() {
    if (threadIdx.x != 0 || blockIdx.x != 0) return;
    float lnf[GG], lef[GG];
    for (int g = 0; g < GG; ++g) {
        double nc = (double)fmaxf(g_small[g], 1.0f);
        lnf[g] = (float)log(nc);
        lef[g] = (float)log1p((double)fmaxf(g_small[GG + g], 0.0f));
    }
    double m0 = 0.0, m1 = 0.0;
    for (int g = 0; g < GG; ++g) { m0 += (double)lnf[g]; m1 += (double)lef[g]; }
    m0 /= GG; m1 /= GG;
    double v0 = 0.0, v1 = 0.0;
    float mn = 3.0e38f, mx = -3.0e38f;
    for (int g = 0; g < GG; ++g) {
        double d0 = (double)lnf[g] - m0, d1 = (double)lef[g] - m1;
        v0 += d0 * d0; v1 += d1 * d1;
        mn = fminf(mn, lnf[g]); mx = fmaxf(mx, lnf[g]);
    }
    double s0 = sqrt(v0 / GG), s1 = sqrt(v1 / GG);
    for (int g = 0; g < GG; ++g) {
        g_small[16 + 2 * g + 0] = (float)(((double)lnf[g] - m0) / (s0 + 1e-6));
        g_small[16 + 2 * g + 1] = (float)(((double)lef[g] - m1) / (s1 + 1e-6));
        g_small[32 + g]         = (float)(((double)lnf[g] - (double)mn) /
                                          ((double)mx - (double)mn + 1e-6));
    }
}

// ---------------- CSR build ----------------
__global__ void deg_kernel(const int* __restrict__ dst) {
    int i = blockIdx.x * blockDim.x + threadIdx.x;
    if (i < EE) atomicAdd(&g_deg[dst[i]], 1);
}

__global__ __launch_bounds__(1024) void csr_scan_kernel() {
    __shared__ int tmp[1024];
    int t = threadIdx.x;
    const int CH = (NN + 1023) / 1024;
    int b0 = t * CH;
    int loc = 0;
    for (int i = 0; i < CH; ++i) {
        int idx = b0 + i;
        if (idx < NN) loc += g_deg[idx];
    }
    tmp[t] = loc;
    __syncthreads();
    for (int off = 1; off < 1024; off <<= 1) {
        int v = (t >= off) ? tmp[t - off] : 0;
        __syncthreads();
        tmp[t] += v;
        __syncthreads();
    }
    int run = tmp[t] - loc;
    for (int i = 0; i < CH; ++i) {
        int idx = b0 + i;
        if (idx < NN) {
            g_start[idx] = run;
            g_cursor[idx] = run;
            run += g_deg[idx];
        }
    }
    if (t == 1023) g_start[NN] = tmp[1023];
}

__global__ void csr_scatter_kernel(const int* __restrict__ src, const int* __restrict__ dst) {
    int i = blockIdx.x * blockDim.x + threadIdx.x;
    if (i < EE) {
        int d = dst[i];
        int pos = atomicAdd(&g_cursor[d], 1);
        g_csrc[pos] = src[i];
    }
}

// ---------------- 256-wide gather: planes in -> planes out; 2 nodes/block ----------------
__global__ __launch_bounds__(128) void gather256_kernel(
    const __nv_bfloat16* __restrict__ fhB, const __nv_bfloat16* __restrict__ flB,
    __nv_bfloat16* __restrict__ ohB, __nv_bfloat16* __restrict__ olB) {
    size_t eoff = (size_t)blockIdx.y * ((size_t)NN * HIDD);
    const uint2* fh2 = (const uint2*)(fhB + eoff);
    const uint2* fl2 = (const uint2*)(flB + eoff);
    __nv_bfloat162* oh = (__nv_bfloat162*)(ohB + eoff);
    __nv_bfloat162* ol = (__nv_bfloat162*)(olB + eoff);
    int n = blockIdx.x * 2 + (threadIdx.x >> 6);
    int tid = threadIdx.x & 63;
    if (n >= NN) return;
    int s = g_start[n], e = g_start[n + 1];
    float4 a0 = make_float4(0.f, 0.f, 0.f, 0.f);
    float4 a1 = make_float4(0.f, 0.f, 0.f, 0.f);
    int j = s;
    for (; j + 2 <= e; j += 2) {
        int s0 = __ldg(&g_csrc[j]), s1 = __ldg(&g_csrc[j + 1]);
        uint2 uh0 = fh2[(size_t)s0 * 64 + tid];
        uint2 ul0 = fl2[(size_t)s0 * 64 + tid];
        uint2 uh1 = fh2[(size_t)s1 * 64 + tid];
        uint2 ul1 = fl2[(size_t)s1 * 64 + tid];
        __nv_bfloat162 h00 = *(__nv_bfloat162*)&uh0.x, h01 = *(__nv_bfloat162*)&uh0.y;
        __nv_bfloat162 l00 = *(__nv_bfloat162*)&ul0.x, l01 = *(__nv_bfloat162*)&ul0.y;
        __nv_bfloat162 h10 = *(__nv_bfloat162*)&uh1.x, h11 = *(__nv_bfloat162*)&uh1.y;
        __nv_bfloat162 l10 = *(__nv_bfloat162*)&ul1.x, l11 = *(__nv_bfloat162*)&ul1.y;
        a0.x += __low2float(h00) + __low2float(l00);
        a0.y += __high2float(h00) + __high2float(l00);
        a0.z += __low2float(h01) + __low2float(l01);
        a0.w += __high2float(h01) + __high2float(l01);
        a1.x += __low2float(h10) + __low2float(l10);
        a1.y += __high2float(h10) + __high2float(l10);
        a1.z += __low2float(h11) + __low2float(l11);
        a1.w += __high2float(h11) + __high2float(l11);
    }
    if (j < e) {
        int s0 = __ldg(&g_csrc[j]);
        uint2 uh0 = fh2[(size_t)s0 * 64 + tid];
        uint2 ul0 = fl2[(size_t)s0 * 64 + tid];
        __nv_bfloat162 h00 = *(__nv_bfloat162*)&uh0.x, h01 = *(__nv_bfloat162*)&uh0.y;
        __nv_bfloat162 l00 = *(__nv_bfloat162*)&ul0.x, l01 = *(__nv_bfloat162*)&ul0.y;
        a0.x += __low2float(h00) + __low2float(l00);
        a0.y += __high2float(h00) + __high2float(l00);
        a0.z += __low2float(h01) + __low2float(l01);
        a0.w += __high2float(h01) + __high2float(l01);
    }
    float4 acc = make_float4(a0.x + a1.x, a0.y + a1.y, a0.z + a1.z, a0.w + a1.w);
    __nv_bfloat16 h0 = __float2bfloat16_rn(acc.x);
    __nv_bfloat16 h1 = __float2bfloat16_rn(acc.y);
    __nv_bfloat16 h2 = __float2bfloat16_rn(acc.z);
    __nv_bfloat16 h3 = __float2bfloat16_rn(acc.w);
    size_t base = (size_t)n * 128 + tid * 2;
    oh[base]     = __nv_bfloat162(h0, h1);
    oh[base + 1] = __nv_bfloat162(h2, h3);
    ol[base]     = __nv_bfloat162(__float2bfloat16_rn(acc.x - __bfloat162float(h0)),
                                  __float2bfloat16_rn(acc.y - __bfloat162float(h1)));
    ol[base + 1] = __nv_bfloat162(__float2bfloat16_rn(acc.z - __bfloat162float(h2)),
                                  __float2bfloat16_rn(acc.w - __bfloat162float(h3)));
}

// ---------------- fused encoder: h = relu(x[:,4:10]@w1+b1) @ w2 + b2, + h hi/lo split ----
// A tiles computed in-kernel from x/w1/b1 (exact same FMA order as separate enc1 kernel).
__global__ __launch_bounds__(256) void gemm256_kernel(
    const float* __restrict__ x, const float* __restrict__ w1enc,
    const float* __restrict__ b1enc,
    const float* __restrict__ W1, const float* __restrict__ bias,
    float* __restrict__ C,
    __nv_bfloat162* __restrict__ Chi, __nv_bfloat162* __restrict__ Clo, int M) {
    __shared__ float As[2][16][68];
    __shared__ float Bs[2][16][68];
    __shared__ float sW1[6][256];
    __shared__ float sB1[256];
    int tid = threadIdx.x;
    int ty = tid >> 4, tx = tid & 15;
    int rowBase = blockIdx.x * 64;
    int colBase = blockIdx.y * 64;

    sB1[tid] = b1enc[tid];
    for (int i = tid; i < 1536; i += 256) sW1[i >> 8][i & 255] = w1enc[i];

    float acc[4][4];
#pragma unroll
    for (int i = 0; i < 4; ++i)
#pragma unroll
        for (int j = 0; j < 4; ++j) acc[i][j] = 0.f;

    int aRow = tid >> 2;
    int aCol = (tid & 3) << 2;
    int bRow = tid >> 4;
    int bCol = (tid & 15) << 2;
    int gARow = min(rowBase + aRow, M - 1);

    // per-thread raw features (row gARow)
    float xv6[6];
#pragma unroll
    for (int k = 0; k < 6; ++k) xv6[k] = x[(size_t)gARow * 16 + 4 + k];

    float4 bvc = *(const float4*)(W1 + (size_t)(0 + bRow) * 256 + colBase + bCol);
    __syncthreads();  // sW1/sB1 ready

#pragma unroll 1
    for (int t = 0; t < 16; ++t) {
        float (*As_)[68] = As[t & 1];
        float (*Bs_)[68] = Bs[t & 1];
        int kt = t * 16;
        // compute A tile elements (enc1 fused; same FMA order as standalone enc1)
        float av[4];
#pragma unroll
        for (int c = 0; c < 4; ++c) {
            int col = kt + aCol + c;
            float v = sB1[col];
#pragma unroll
            for (int k = 0; k < 6; ++k) v += xv6[k] * sW1[k][col];
            av[c] = fmaxf(v, 0.f);
        }
        As_[aCol + 0][aRow] = av[0];
        As_[aCol + 1][aRow] = av[1];
        As_[aCol + 2][aRow] = av[2];
        As_[aCol + 3][aRow] = av[3];
        *(float4*)&Bs_[bRow][bCol] = bvc;
        if (t < 15) {
            int ktn = (t + 1) * 16;
            bvc = *(const float4*)(W1 + (size_t)(ktn + bRow) * 256 + colBase + bCol);
        }
        __syncthreads();
#pragma unroll
        for (int k = 0; k < 16; ++k) {
            float4 a = *(const float4*)&As_[k][ty * 4];
            float4 b = *(const float4*)&Bs_[k][tx * 4];
            acc[0][0] += a.x * b.x; acc[0][1] += a.x * b.y; acc[0][2] += a.x * b.z; acc[0][3] += a.x * b.w;
            acc[1][0] += a.y * b.x; acc[1][1] += a.y * b.y; acc[1][2] += a.y * b.z; acc[1][3] += a.y * b.w;
            acc[2][0] += a.z * b.x; acc[2][1] += a.z * b.y; acc[2][2] += a.z * b.z; acc[2][3] += a.z * b.w;
            acc[3][0] += a.w * b.x; acc[3][1] += a.w * b.y; acc[3][2] += a.w * b.z; acc[3][3] += a.w * b.w;
        }
    }
    int col0 = colBase + tx * 4;
    float4 bv = *(const float4*)(bias + col0);
#pragma unroll
    for (int i = 0; i < 4; ++i) {
        int row = rowBase + ty * 4 + i;
        if (row < M) {
            float4 o;
            o.x = acc[i][0] + bv.x;
            o.y = acc[i][1] + bv.y;
            o.z = acc[i][2] + bv.z;
            o.w = acc[i][3] + bv.w;
            *(float4*)(C + (size_t)row * 256 + col0) = o;
            __nv_bfloat16 h0 = __float2bfloat16_rn(o.x);
            __nv_bfloat16 h1 = __float2bfloat16_rn(o.y);
            __nv_bfloat16 h2 = __float2bfloat16_rn(o.z);
            __nv_bfloat16 h3 = __float2bfloat16_rn(o.w);
            size_t b2i = ((size_t)row * 256 + col0) >> 1;
            Chi[b2i]     = __nv_bfloat162(h0, h1);
            Chi[b2i + 1] = __nv_bfloat162(h2, h3);
            Clo[b2i]     = __nv_bfloat162(__float2bfloat16_rn(o.x - __bfloat162float(h0)),
                                          __float2bfloat16_rn(o.y - __bfloat162float(h1)));
            Clo[b2i + 1] = __nv_bfloat162(__float2bfloat16_rn(o.z - __bfloat162float(h2)),
                                          __float2bfloat16_rn(o.w - __bfloat162float(h3)));
        }
    }
}

// ---------------- weight split+transpose ----------------
__global__ void convert_weights_kernel(const float* __restrict__ w_rel,
                                       const float* __restrict__ w_root) {
    int id = blockIdx.x * blockDim.x + threadIdx.x;
    int slot = id >> 16;
    int r = id & 65535;
    int n = r >> 8, k = r & 255;
    const float* base = (slot < 8) ? (w_rel + (size_t)slot * 65536)
                                   : (w_root + (size_t)(slot - 8) * 65536);
    float v = base[(size_t)k * 256 + n];
    __nv_bfloat16 hi = __float2bfloat16_rn(v);
    float rest = v - __bfloat162float(hi);
    g_wth[(size_t)slot * 65536 + n * 256 + k] = hi;
    g_wtl[(size_t)slot * 65536 + n * 256 + k] = __float2bfloat16_rn(rest);
}

// ---------------- batched tensor-core split-bf16 dual GEMM (128x128, double-buffered) ----
#define MMA_BF16(D, A, B0, B1)                                                        \
    asm volatile(                                                                     \
        "mma.sync.aligned.m16n8k16.row.col.f32.bf16.bf16.f32 "                        \
        "{%0,%1,%2,%3},{%4,%5,%6,%7},{%8,%9},{%0,%1,%2,%3};\n"                        \
        : "+f"((D)[0]), "+f"((D)[1]), "+f"((D)[2]), "+f"((D)[3])                      \
        : "r"((A)[0]), "r"((A)[1]), "r"((A)[2]), "r"((A)[3]), "r"(B0), "r"(B1))

#define SM_BUF   40960
#define SM_AH    0
#define SM_AL    10240
#define SM_WH    20480
#define SM_WL    30720
#define GEMM_SMEM (2 * SM_BUF)

__global__ __launch_bounds__(256) void expert_gemm_kernel(
    const __nv_bfloat16* __restrict__ A1hB, const __nv_bfloat16* __restrict__ A1lB,
    const __nv_bfloat16* __restrict__ A2hB, const __nv_bfloat16* __restrict__ A2lB,
    const __nv_bfloat16* __restrict__ WthB, const __nv_bfloat16* __restrict__ WtlB,
    const float* __restrict__ brel, float* __restrict__ CB,
    __nv_bfloat16* __restrict__ ChiB, __nv_bfloat16* __restrict__ CloB,
    int layer, int M) {
    extern __shared__ char dynsm[];
    int e = blockIdx.z;
    const size_t NH_ = (size_t)NN * HIDD;
    size_t aoff = layer ? (size_t)e * NH_ : 0;
    const __nv_bfloat16* Ah[2] = {A1hB + aoff, A2hB + aoff};
    const __nv_bfloat16* Al[2] = {A1lB + aoff, A2lB + aoff};
    int sRel = e * 2 + layer, sRoot = 8 + e * 2 + layer;
    const __nv_bfloat16* Wh[2] = {WthB + (size_t)sRel * 65536, WthB + (size_t)sRoot * 65536};
    const __nv_bfloat16* Wl[2] = {WtlB + (size_t)sRel * 65536, WtlB + (size_t)sRoot * 65536};
    const float* bias = brel + (size_t)(e * 2 + layer) * 256;
    float* C = CB ? (CB + (size_t)e * NH_) : nullptr;
    __nv_bfloat162* Chi = ChiB ? (__nv_bfloat162*)(ChiB + (size_t)e * NH_) : nullptr;
    __nv_bfloat162* Clo = CloB ? (__nv_bfloat162*)(CloB + (size_t)e * NH_) : nullptr;

    int tid = threadIdx.x;
    int lane = tid & 31, w = tid >> 5;
    int warpM0 = (w & 1) * 64;      // 2 warps in M
    int warpN0 = (w >> 1) * 32;     // 4 warps in N
    int blockM0 = blockIdx.x * 128;
    int blockN0 = blockIdx.y * 128;
    int g = lane >> 2, q = lane & 3;
    int arow = tid >> 1;            // 0..127
    int ak8 = (tid & 1) * 16;       // 0 or 16
    int gr = min(blockM0 + arow, M - 1);

    float d[4][4][4];
#pragma unroll
    for (int mt = 0; mt < 4; ++mt)
#pragma unroll
        for (int nt = 0; nt < 4; ++nt)
#pragma unroll
            for (int i = 0; i < 4; ++i) d[mt][nt][i] = 0.f;

    float4 cur[8];
    {
        const int kc = 0;
        cur[0] = *(const float4*)(Ah[0] + (size_t)gr * 256 + kc + ak8);
        cur[1] = *(const float4*)(Ah[0] + (size_t)gr * 256 + kc + ak8 + 8);
        cur[2] = *(const float4*)(Al[0] + (size_t)gr * 256 + kc + ak8);
        cur[3] = *(const float4*)(Al[0] + (size_t)gr * 256 + kc + ak8 + 8);
        cur[4] = *(const float4*)(Wh[0] + (size_t)(blockN0 + arow) * 256 + kc + ak8);
        cur[5] = *(const float4*)(Wh[0] + (size_t)(blockN0 + arow) * 256 + kc + ak8 + 8);
        cur[6] = *(const float4*)(Wl[0] + (size_t)(blockN0 + arow) * 256 + kc + ak8);
        cur[7] = *(const float4*)(Wl[0] + (size_t)(blockN0 + arow) * 256 + kc + ak8 + 8);
    }

#pragma unroll 1
    for (int t = 0; t < 16; ++t) {
        char* buf = dynsm + (t & 1) * SM_BUF;
        __nv_bfloat16* bAh = (__nv_bfloat16*)(buf + SM_AH);
        __nv_bfloat16* bAl = (__nv_bfloat16*)(buf + SM_AL);
        __nv_bfloat16* bWh = (__nv_bfloat16*)(buf + SM_WH);
        __nv_bfloat16* bWl = (__nv_bfloat16*)(buf + SM_WL);
        *(float4*)&bAh[arow * 40 + ak8]     = cur[0];
        *(float4*)&bAh[arow * 40 + ak8 + 8] = cur[1];
        *(float4*)&bAl[arow * 40 + ak8]     = cur[2];
        *(float4*)&bAl[arow * 40 + ak8 + 8] = cur[3];
        *(float4*)&bWh[arow * 40 + ak8]     = cur[4];
        *(float4*)&bWh[arow * 40 + ak8 + 8] = cur[5];
        *(float4*)&bWl[arow * 40 + ak8]     = cur[6];
        *(float4*)&bWl[arow * 40 + ak8 + 8] = cur[7];
        if (t < 15) {
            int tn = t + 1;
            int pass = tn >> 3, kc = (tn & 7) * 32;
            cur[0] = *(const float4*)(Ah[pass] + (size_t)gr * 256 + kc + ak8);
            cur[1] = *(const float4*)(Ah[pass] + (size_t)gr * 256 + kc + ak8 + 8);
            cur[2] = *(const float4*)(Al[pass] + (size_t)gr * 256 + kc + ak8);
            cur[3] = *(const float4*)(Al[pass] + (size_t)gr * 256 + kc + ak8 + 8);
            cur[4] = *(const float4*)(Wh[pass] + (size_t)(blockN0 + arow) * 256 + kc + ak8);
            cur[5] = *(const float4*)(Wh[pass] + (size_t)(blockN0 + arow) * 256 + kc + ak8 + 8);
            cur[6] = *(const float4*)(Wl[pass] + (size_t)(blockN0 + arow) * 256 + kc + ak8);
            cur[7] = *(const float4*)(Wl[pass] + (size_t)(blockN0 + arow) * 256 + kc + ak8 + 8);
        }
        __syncthreads();
#pragma unroll
        for (int ks = 0; ks < 32; ks += 16) {
            int k0 = ks + q * 2;
            unsigned ah[4][4], al[4][4];
#pragma unroll
            for (int mt = 0; mt < 4; ++mt) {
                int r = warpM0 + mt * 16 + g;
                ah[mt][0] = *(const unsigned*)&bAh[r * 40 + k0];
                ah[mt][1] = *(const unsigned*)&bAh[(r + 8) * 40 + k0];
                ah[mt][2] = *(const unsigned*)&bAh[r * 40 + k0 + 8];
                ah[mt][3] = *(const unsigned*)&bAh[(r + 8) * 40 + k0 + 8];
                al[mt][0] = *(const unsigned*)&bAl[r * 40 + k0];
                al[mt][1] = *(const unsigned*)&bAl[(r + 8) * 40 + k0];
                al[mt][2] = *(const unsigned*)&bAl[r * 40 + k0 + 8];
                al[mt][3] = *(const unsigned*)&bAl[(r + 8) * 40 + k0 + 8];
            }
#pragma unroll
            for (int nt = 0; nt < 4; ++nt) {
                int n = warpN0 + nt * 8 + g;
                unsigned bh0 = *(const unsigned*)&bWh[n * 40 + k0];
                unsigned bh1 = *(const unsigned*)&bWh[n * 40 + k0 + 8];
                unsigned bl0 = *(const unsigned*)&bWl[n * 40 + k0];
                unsigned bl1 = *(const unsigned*)&bWl[n * 40 + k0 + 8];
#pragma unroll
                for (int mt = 0; mt < 4; ++mt) {
                    MMA_BF16(d[mt][nt], ah[mt], bh0, bh1);
                    MMA_BF16(d[mt][nt], ah[mt], bl0, bl1);
                    MMA_BF16(d[mt][nt], al[mt], bh0, bh1);
                }
            }
        }
    }
#pragma unroll
    for (int mt = 0; mt < 4; ++mt) {
        int r = blockM0 + warpM0 + mt * 16 + g;
#pragma unroll
        for (int nt = 0; nt < 4; ++nt) {
            int col = blockN0 + warpN0 + nt * 8 + q * 2;
            float b0 = bias[col], b1 = bias[col + 1];
#pragma unroll
            for (int half = 0; half < 2; ++half) {
                int rr = r + half * 8;
                if (rr < M) {
                    float ox = fmaxf(d[mt][nt][half * 2 + 0] + b0, 0.f);
                    float oy = fmaxf(d[mt][nt][half * 2 + 1] + b1, 0.f);
                    if (C) *(float2*)(C + (size_t)rr * 256 + col) = make_float2(ox, oy);
                    if (Chi) {
                        __nv_bfloat16 h0 = __float2bfloat16_rn(ox);
                        __nv_bfloat16 h1 = __float2bfloat16_rn(oy);
                        size_t b2i = ((size_t)rr * 256 + col) >> 1;
                        Chi[b2i] = __nv_bfloat162(h0, h1);
                        Clo[b2i] = __nv_bfloat162(
                            __float2bfloat16_rn(ox - __bfloat162float(h0)),
                            __float2bfloat16_rn(oy - __bfloat162float(h1)));
                    }
                }
            }
        }
    }
}

// ---------------- compensated accumulation: TwoProd + Kahan ----------------
__device__ __forceinline__ void kacc(float& s, float& c, float a, float b) {
    float p = __fmul_rn(a, b);
    float e = __fmaf_rn(a, b, -p);
    float y = __fadd_rn(p, -c);
    float t = __fadd_rn(s, y);
    c = __fadd_rn(__fadd_rn(t, -s), -y);
    c = __fadd_rn(c, -e);
    s = t;
}
// final value = s - c

// ---------------- fast router (fp32) + tie flagging ----------------
#define TIE_TAU 1e-3f

__global__ __launch_bounds__(128) void router_fast_kernel(
    const float* __restrict__ h, const int* __restrict__ batch,
    const float* __restrict__ w1, const float* __restrict__ b1,
    const float* __restrict__ lng, const float* __restrict__ lnb,
    const float* __restrict__ w2, const float* __restrict__ b2,
    const float* __restrict__ centers, float* __restrict__ sw) {
    __shared__ float sh[8][260];
    __shared__ float rbuf[8][128];
    __shared__ float smu[8], srs[8], snl[8];
    __shared__ float slog[8][4];
    int node0 = blockIdx.x * 8;
    int tid = threadIdx.x;
    for (int r = 0; r < 8; ++r) {
        int node = node0 + r;
        if (node < NN) {
            for (int k = tid; k < 256; k += 128) sh[r][k] = h[(size_t)node * 256 + k];
            if (tid == 0) {
                int b = batch[node];
                sh[r][256] = g_small[16 + 2 * b + 0];
                sh[r][257] = g_small[16 + 2 * b + 1];
                snl[r] = g_small[32 + b];
            }
        }
    }
    __syncthreads();
    float acc[8];
#pragma unroll
    for (int r = 0; r < 8; ++r) acc[r] = 0.f;
    for (int k = 0; k < 258; ++k) {
        float wv = w1[k * 128 + tid];
#pragma unroll
        for (int r = 0; r < 8; ++r) acc[r] = __fmaf_rn(sh[r][k], wv, acc[r]);
    }
    float bb = b1[tid];
    float rv[8];
#pragma unroll
    for (int r = 0; r < 8; ++r) { rv[r] = acc[r] + bb; rbuf[r][tid] = rv[r]; }
    __syncthreads();
    int wid = tid >> 5, lane = tid & 31;
    for (int rr = 0; rr < 2; ++rr) {
        int r = wid * 2 + rr;
        float a0 = rbuf[r][lane], a1 = rbuf[r][lane + 32], a2 = rbuf[r][lane + 64], a3 = rbuf[r][lane + 96];
        float s = a0 + a1 + a2 + a3;
#pragma unroll
        for (int off = 16; off; off >>= 1) s += __shfl_down_sync(0xffffffffu, s, off);
        float mu = __shfl_sync(0xffffffffu, s, 0) * (1.0f / 128.0f);
        float d0 = a0 - mu, d1 = a1 - mu, d2 = a2 - mu, d3 = a3 - mu;
        float v = d0 * d0 + d1 * d1 + d2 * d2 + d3 * d3;
#pragma unroll
        for (int off = 16; off; off >>= 1) v += __shfl_down_sync(0xffffffffu, v, off);
        if (lane == 0) {
            smu[r] = mu;
            float varf = v * (1.0f / 128.0f) + 1e-5f;
            srs[r] = (float)(1.0 / sqrt((double)varf));
        }
    }
    __syncthreads();
    float gch = lng[tid], bch = lnb[tid];
#pragma unroll
    for (int r = 0; r < 8; ++r) {
        float v = (rv[r] - smu[r]) * srs[r] * gch + bch;
        rbuf[r][tid] = fmaxf(v, 0.f);
    }
    __syncthreads();
    if (tid < 32) {
        int r = tid >> 2, ne = tid & 3;
        float s = 0.f;
        for (int j = 0; j < 128; ++j) s = __fmaf_rn(rbuf[r][j], w2[j * 4 + ne], s);
        float learned = s + b2[ne];
        float d = snl[r] - centers[ne];
        slog[r][ne] = 0.65f * learned - 0.35f * d * d;
    }
    __syncthreads();
    if (tid < 8) {
        int node = node0 + tid;
        if (node < NN) {
            float lg[4];
#pragma unroll
            for (int ne = 0; ne < 4; ++ne) lg[ne] = slog[tid][ne];
            int i1 = 0;
#pragma unroll
            for (int ne = 1; ne < 4; ++ne) if (lg[ne] > lg[i1]) i1 = ne;
            int i2 = -1;
#pragma unroll
            for (int ne = 0; ne < 4; ++ne) if (ne != i1 && (i2 < 0 || lg[ne] > lg[i2])) i2 = ne;
            int i3 = -1;
#pragma unroll
            for (int ne = 0; ne < 4; ++ne) if (ne != i1 && ne != i2 && (i3 < 0 || lg[ne] > lg[i3])) i3 = ne;
            float mx = lg[i1];
            float p[4], sum = 0.f;
#pragma unroll
            for (int ne = 0; ne < 4; ++ne) { p[ne] = __expf(lg[ne] - mx); sum += p[ne]; }
            float inv = 1.0f / sum;
            float v1 = p[i1] * inv, v2 = p[i2] * inv;
            float norm = 1.0f / (v1 + v2 + 1e-8f);
            float o[4] = {0.f, 0.f, 0.f, 0.f};
            o[i1] = v1 * norm; o[i2] = v2 * norm;
#pragma unroll
            for (int ne = 0; ne < 4; ++ne) sw[(size_t)node * 4 + ne] = o[ne];
            if (lg[i2] - lg[i3] < TIE_TAU) {
                int pos = atomicAdd(&g_nflag, 1);
                g_flag[pos] = node;
            }
        }
    }
}

// ---------------- exact router fixup for flagged (near-tie) nodes ----------------
__global__ __launch_bounds__(128) void router_fix_kernel(
    const float* __restrict__ h, const int* __restrict__ batch,
    const float* __restrict__ w1, const float* __restrict__ b1,
    const float* __restrict__ lng, const float* __restrict__ lnb,
    const float* __restrict__ w2, const float* __restrict__ b2,
    const float* __restrict__ centers, float* __restrict__ sw) {
    __shared__ float sh[260];
    __shared__ float rbuf[128];
    __shared__ float red[8];
    __shared__ float snl1;
    __shared__ double slogd[4];
    int tid = threadIdx.x;
    int wid = tid >> 5, lane = tid & 31;
    int nflag = g_nflag;
    for (int fi = blockIdx.x; fi < nflag; fi += gridDim.x) {
        int node = g_flag[fi];
        for (int k = tid; k < 256; k += 128) sh[k] = h[(size_t)node * 256 + k];
        if (tid == 0) {
            int b = batch[node];
            sh[256] = g_small[16 + 2 * b + 0];
            sh[257] = g_small[16 + 2 * b + 1];
            snl1 = g_small[32 + b];
        }
        __syncthreads();
        float s = 0.f, c = 0.f;
        for (int k = 0; k < 258; ++k) kacc(s, c, sh[k], w1[k * 128 + tid]);
        float rv = (s - c) + b1[tid];
        float v = rv;
#pragma unroll
        for (int off = 16; off; off >>= 1) v += __shfl_down_sync(0xffffffffu, v, off);
        if (lane == 0) red[wid] = v;
        __syncthreads();
        float mu = (red[0] + red[1] + red[2] + red[3]) * (1.0f / 128.0f);
        float dd = rv - mu;
        float vv = dd * dd;
#pragma unroll
        for (int off = 16; off; off >>= 1) vv += __shfl_down_sync(0xffffffffu, vv, off);
        if (lane == 0) red[4 + wid] = vv;
        __syncthreads();
        float var = (red[4] + red[5] + red[6] + red[7]) * (1.0f / 128.0f) + 1e-5f;
        float rs = (float)(1.0 / sqrt((double)var));
        rbuf[tid] = fmaxf((rv - mu) * rs * lng[tid] + lnb[tid], 0.f);
        __syncthreads();
        if (tid < 4) {
            float ss = 0.f, cc = 0.f;
            for (int j = 0; j < 128; ++j) kacc(ss, cc, rbuf[j], w2[j * 4 + tid]);
            float learned = (ss - cc) + b2[tid];
            double d = (double)snl1 - (double)centers[tid];
            slogd[tid] = 0.65 * (double)learned - 0.35 * d * d;
        }
        __syncthreads();
        if (tid == 0) {
            double lg[4];
#pragma unroll
            for (int ne = 0; ne < 4; ++ne) lg[ne] = slogd[ne];
            double mx = lg[0];
#pragma unroll
            for (int ne = 1; ne < 4; ++ne) mx = fmax(mx, lg[ne]);
            double pd[4], sum = 0.0;
#pragma unroll
            for (int ne = 0; ne < 4; ++ne) { pd[ne] = exp(lg[ne] - mx); sum += pd[ne]; }
            float p[4];
#pragma unroll
            for (int ne = 0; ne < 4; ++ne) p[ne] = (float)(pd[ne] / sum);
            int i1 = 0;
#pragma unroll
            for (int ne = 1; ne < 4; ++ne) if (lg[ne] > lg[i1]) i1 = ne;
            int i2 = -1;
#pragma unroll
            for (int ne = 0; ne < 4; ++ne) if (ne != i1 && (i2 < 0 || lg[ne] > lg[i2])) i2 = ne;
            float v1 = p[i1], v2 = p[i2];
            float norm = 1.0f / (v1 + v2 + 1e-8f);
            float o[4] = {0.f, 0.f, 0.f, 0.f};
            o[i1] = v1 * norm; o[i2] = v2 * norm;
#pragma unroll
            for (int ne = 0; ne < 4; ++ne) sw[(size_t)node * 4 + ne] = o[ne];
        }
        __syncthreads();
    }
}

// ---------------- vu projection (batched over experts via blockIdx.y) ----------------
__global__ __launch_bounds__(256) void vu_kernel(
    const float* __restrict__ xe2B,
    const float* __restrict__ wroB,
    const float* __restrict__ wrtB,
    float* __restrict__ vbuf,
    float* __restrict__ ubuf) {
    __shared__ float sWv[8][260];
    __shared__ float sWu[8][260];
    int e = blockIdx.y;
    const float* xe2 = xe2B + (size_t)e * NN * HIDD;
    const float* wro = wroB + (size_t)e * 1536;
    const float* wrt = wrtB + (size_t)e * 1536;
    int t = threadIdx.x;
    for (int i = t; i < 1536; i += 256) {
        int k = i / 6, j = i % 6;
        sWv[j][k] = wro[i];
        sWu[j][k] = wrt[i];
    }
    __syncthreads();
    int nloc = t >> 3, j = t & 7;
    int n = blockIdx.x * 32 + nloc;
    if (n >= NN) return;
    float v = 0.f, u = 0.f;
    if (j < 6) {
        const float4* xr = (const float4*)(xe2 + (size_t)n * 256);
#pragma unroll 4
        for (int k4 = 0; k4 < 64; ++k4) {
            float4 xv = xr[k4];
            int k = k4 * 4;
            v += xv.x * sWv[j][k] + xv.y * sWv[j][k + 1] + xv.z * sWv[j][k + 2] + xv.w * sWv[j][k + 3];
            u += xv.x * sWu[j][k] + xv.y * sWu[j][k + 1] + xv.z * sWu[j][k + 2] + xv.w * sWu[j][k + 3];
        }
    }
    vbuf[(size_t)n * 32 + e * 8 + j] = v;
    ubuf[(size_t)n * 32 + e * 8 + j] = u;
}

// ---------------- final output ----------------
__global__ __launch_bounds__(256) void out_final_kernel(
    const float* __restrict__ vbuf, const float* __restrict__ ubuf,
    const float* __restrict__ sw, const float* __restrict__ bro,
    float* __restrict__ out) {
    int warp = (blockIdx.x * 256 + threadIdx.x) >> 5;
    int lane = threadIdx.x & 31;
    if (warp >= NN) return;
    int e = lane >> 3, j = lane & 7;
    int s = g_start[warp], en = g_start[warp + 1];
    float sum0 = 0.f, sum1 = 0.f;
    int jj = s;
    for (; jj + 2 <= en; jj += 2) {
        int s0 = __ldg(&g_csrc[jj]), s1 = __ldg(&g_csrc[jj + 1]);
        sum0 += vbuf[(size_t)s0 * 32 + lane];
        sum1 += vbuf[(size_t)s1 * 32 + lane];
    }
    if (jj < en) sum0 += vbuf[(size_t)__ldg(&g_csrc[jj]) * 32 + lane];
    float sum = sum0 + sum1;
    float u = ubuf[(size_t)warp * 32 + lane];
    float bj = (j < 6) ? bro[e * 6 + j] : 0.f;
    float swv = sw[(size_t)warp * 4 + e];
    float val = swv * (sum + u + bj);
    val += __shfl_down_sync(0xffffffffu, val, 16);
    val += __shfl_down_sync(0xffffffffu, val, 8);
    if (lane < 6) out[(size_t)warp * 6 + lane] = val;
}

// ---------------- host launch ----------------
extern "C" void kernel_launch(void* const* d_in, const int* in_sizes, int n_in,
                              void* d_out, int out_size) {
    const float* x       = (const float*)d_in[0];
    const int*   ei      = (const int*)d_in[1];
    const int*   batch   = (const int*)d_in[2];
    const float* enc_w1  = (const float*)d_in[4];
    const float* enc_b1  = (const float*)d_in[5];
    const float* enc_w2  = (const float*)d_in[6];
    const float* enc_b2  = (const float*)d_in[7];
    const float* rt_w1   = (const float*)d_in[8];
    const float* rt_b1   = (const float*)d_in[9];
    const float* ln_g    = (const float*)d_in[10];
    const float* ln_b    = (const float*)d_in[11];
    const float* rt_w2   = (const float*)d_in[12];
    const float* rt_b2   = (const float*)d_in[13];
    const float* centers = (const float*)d_in[14];
    const float* w_rel   = (const float*)d_in[15];
    const float* b_rel   = (const float*)d_in[16];
    const float* w_root  = (const float*)d_in[17];
    const float* w_rout  = (const float*)d_in[18];
    const float* b_rout  = (const float*)d_in[19];
    const float* w_rtout = (const float*)d_in[20];
    float* out = (float*)d_out;

    static float *ph = nullptr, *psw, *psmall, *pxe2f, *pvbuf, *pubuf;
    static __nv_bfloat16 *p0h, *p0l, *p1h, *p1l, *pxeh, *pxel, *pagh, *pagl, *pwh, *pwl;
    static int* pdeg;
    static cudaStream_t sB = nullptr, sC = nullptr;
    static cudaEvent_t evRoot, evStats, evW, evH, evAggh, evRouter;
    static cudaEvent_t evL1, evG, evL2, evVU;
    if (!ph) {
        cudaGetSymbolAddress((void**)&ph,     g_h);
        cudaGetSymbolAddress((void**)&psw,    g_sw);
        cudaGetSymbolAddress((void**)&psmall, g_small);
        cudaGetSymbolAddress((void**)&p0h, g_p0h);
        cudaGetSymbolAddress((void**)&p0l, g_p0l);
        cudaGetSymbolAddress((void**)&p1h, g_p1h);
        cudaGetSymbolAddress((void**)&p1l, g_p1l);
        cudaGetSymbolAddress((void**)&pxeh, g_xeh);
        cudaGetSymbolAddress((void**)&pxel, g_xel);
        cudaGetSymbolAddress((void**)&pagh, g_agh);
        cudaGetSymbolAddress((void**)&pagl, g_agl);
        cudaGetSymbolAddress((void**)&pxe2f, g_xe2f);
        cudaGetSymbolAddress((void**)&pvbuf, g_vbuf);
        cudaGetSymbolAddress((void**)&pubuf, g_ubuf);
        cudaGetSymbolAddress((void**)&pwh, g_wth);
        cudaGetSymbolAddress((void**)&pwl, g_wtl);
        cudaGetSymbolAddress((void**)&pdeg, g_deg);
        cudaFuncSetAttribute(expert_gemm_kernel,
                             cudaFuncAttributeMaxDynamicSharedMemorySize, GEMM_SMEM);
        cudaStreamCreateWithFlags(&sB, cudaStreamNonBlocking);
        cudaStreamCreateWithFlags(&sC, cudaStreamNonBlocking);
        cudaEventCreateWithFlags(&evRoot,   cudaEventDisableTiming);
        cudaEventCreateWithFlags(&evStats,  cudaEventDisableTiming);
        cudaEventCreateWithFlags(&evW,      cudaEventDisableTiming);
        cudaEventCreateWithFlags(&evH,      cudaEventDisableTiming);
        cudaEventCreateWithFlags(&evAggh,   cudaEventDisableTiming);
        cudaEventCreateWithFlags(&evRouter, cudaEventDisableTiming);
        cudaEventCreateWithFlags(&evL1, cudaEventDisableTiming);
        cudaEventCreateWithFlags(&evG,  cudaEventDisableTiming);
        cudaEventCreateWithFlags(&evL2, cudaEventDisableTiming);
        cudaEventCreateWithFlags(&evVU, cudaEventDisableTiming);
    }

    const int* src = ei;
    const int* dst = ei + EE;

    // fork
    cudaEventRecord(evRoot, 0);
    cudaStreamWaitEvent(sB, evRoot, 0);
    cudaStreamWaitEvent(sC, evRoot, 0);

    // ---- stream A (default): fused encoder ----
    dim3 ggrid((NN + 63) / 64, 4);
    gemm256_kernel<<<ggrid, 256>>>(x, enc_w1, enc_b1, enc_w2, enc_b2, ph,
                                   (__nv_bfloat162*)p1h, (__nv_bfloat162*)p1l, NN);
    cudaEventRecord(evH, 0);

    // ---- stream B: stats + CSR + weight split ----
    zero_kernel<<<1, 32, 0, sB>>>(psmall, 64);
    zero_kernel<<<(NN / 4 + 255) / 256, 256, 0, sB>>>((float*)pdeg, NN);
    count_nodes_kernel<<<(NN + 255) / 256, 256, 0, sB>>>(batch);
    count_edges_kernel<<<(EE + 255) / 256, 256, 0, sB>>>(src, batch);
    stats_finalize_kernel<<<1, 32, 0, sB>>>();
    cudaEventRecord(evStats, sB);
    deg_kernel<<<(EE + 255) / 256, 256, 0, sB>>>(dst);
    csr_scan_kernel<<<1, 1024, 0, sB>>>();
    csr_scatter_kernel<<<(EE + 255) / 256, 256, 0, sB>>>(src, dst);
    convert_weights_kernel<<<(16 * 65536) / 256, 256, 0, sB>>>(w_rel, w_root);
    cudaEventRecord(evW, sB);

    // ---- stream C: two-pass router ----
    cudaStreamWaitEvent(sC, evStats, 0);
    cudaStreamWaitEvent(sC, evH, 0);
    zero_nflag_kernel<<<1, 32, 0, sC>>>();
    router_fast_kernel<<<(NN + 7) / 8, 128, 0, sC>>>(ph, batch, rt_w1, rt_b1, ln_g, ln_b,
                                                     rt_w2, rt_b2, centers, psw);
    router_fix_kernel<<<64, 128, 0, sC>>>(ph, batch, rt_w1, rt_b1, ln_g, ln_b,
                                          rt_w2, rt_b2, centers, psw);
    cudaEventRecord(evRouter, sC);

    // ---- B: aggh gather (h planes -> aggh planes) ----
    cudaStreamWaitEvent(sB, evH, 0);
    gather256_kernel<<<dim3((NN + 1) / 2, 1), 128, 0, sB>>>(p1h, p1l, p0h, p0l);
    cudaEventRecord(evAggh, sB);

    // ---- A: batched expert L1 GEMM (z = expert) ----
    cudaStreamWaitEvent(0, evW, 0);
    cudaStreamWaitEvent(0, evAggh, 0);
    dim3 tcgrid((NN + 127) / 128, 2, NEXP);
    expert_gemm_kernel<<<tcgrid, 256, GEMM_SMEM>>>(p0h, p0l, p1h, p1l, pwh, pwl,
                                                   b_rel, nullptr, pxeh, pxel, 0, NN);
    cudaEventRecord(evL1, 0);

    // ---- B: batched xe gathers (y = expert) ----
    cudaStreamWaitEvent(sB, evL1, 0);
    gather256_kernel<<<dim3((NN + 1) / 2, NEXP), 128, 0, sB>>>(pxeh, pxel, pagh, pagl);
    cudaEventRecord(evG, sB);

    // ---- A: batched expert L2 GEMM ----
    cudaStreamWaitEvent(0, evG, 0);
    expert_gemm_kernel<<<tcgrid, 256, GEMM_SMEM>>>(pagh, pagl, pxeh, pxel, pwh, pwl,
                                                   b_rel, pxe2f, nullptr, nullptr, 1, NN);
    cudaEventRecord(evL2, 0);

    // ---- B: batched vu projections ----
    cudaStreamWaitEvent(sB, evL2, 0);
    vu_kernel<<<dim3((NN + 31) / 32, NEXP), 256, 0, sB>>>(pxe2f, w_rout, w_rtout,
                                                          pvbuf, pubuf);
    cudaEventRecord(evVU, sB);

    // ---- A: final output ----
    cudaStreamWaitEvent(0, evRouter, 0);
    cudaStreamWaitEvent(0, evVU, 0);
    out_final_kernel<<<(NN * 32 + 255) / 256, 256>>>(pvbuf, pubuf, psw, b_rout, out);
}

// round 15
// speedup vs baseline: 1.0119x; 1.0119x over previous
#include <cuda_runtime.h>
#include <cuda_bf16.h>
#include <math.h>

#define NN   50000
#define EE   800000
#define GG   8
#define HIDD 256
#define RHH  128
#define NEXP 4
#define OUTD 6

// ---------------- scratch (static device globals; no allocation) ----------------
__device__ float g_h   [(size_t)NN * HIDD];
__device__ float g_sw  [(size_t)NN * NEXP];
__device__ float g_small[64];

// CSR by dst
__device__ int g_deg   [NN];
__device__ int g_start [NN + 1];
__device__ int g_cursor[NN];
__device__ int g_csrc  [EE];

// router tie-fixup list
__device__ int g_nflag;
__device__ int g_flag[NN];

// shared split planes
__device__ __nv_bfloat16 g_p0h[(size_t)NN * HIDD];  // aggh hi
__device__ __nv_bfloat16 g_p0l[(size_t)NN * HIDD];  // aggh lo
__device__ __nv_bfloat16 g_p1h[(size_t)NN * HIDD];  // h hi
__device__ __nv_bfloat16 g_p1l[(size_t)NN * HIDD];  // h lo
// per-expert buffers
__device__ __nv_bfloat16 g_xeh[(size_t)NEXP * NN * HIDD];  // xe hi
__device__ __nv_bfloat16 g_xel[(size_t)NEXP * NN * HIDD];  // xe lo
__device__ __nv_bfloat16 g_agh[(size_t)NEXP * NN * HIDD];  // agg hi
__device__ __nv_bfloat16 g_agl[(size_t)NEXP * NN * HIDD];  // agg lo
__device__ float g_xe2f[(size_t)NEXP * NN * HIDD];         // xe2 fp32
// projected outputs: [N][4 experts][8 cols]
__device__ float g_vbuf[(size_t)NN * 32];
__device__ float g_ubuf[(size_t)NN * 32];
// transposed split weights: slot = e*2+l for w_rel, 8+e*2+l for w_root; [slot][n][k]
__device__ __nv_bfloat16 g_wth[16 * 65536];
__device__ __nv_bfloat16 g_wtl[16 * 65536];

// ---------------- utility ----------------
__global__ void zero_kernel(float* __restrict__ p, int n) {
    int i = (blockIdx.x * blockDim.x + threadIdx.x) * 4;
    if (i + 3 < n) {
        *(float4*)(p + i) = make_float4(0.f, 0.f, 0.f, 0.f);
    } else {
        for (int j = i; j < n; ++j) p[j] = 0.f;
    }
}

__global__ void zero_nflag_kernel() {
    if (threadIdx.x == 0) g_nflag = 0;
}

// ---------------- graph stats ----------------
__global__ void count_nodes_kernel(const int* __restrict__ batch) {
    __shared__ float c[GG];
    if (threadIdx.x < GG) c[threadIdx.x] = 0.f;
    __syncthreads();
    int i = blockIdx.x * blockDim.x + threadIdx.x;
    if (i < NN) atomicAdd(&c[batch[i]], 1.0f);
    __syncthreads();
    if (threadIdx.x < GG && c[threadIdx.x] != 0.f)
        atomicAdd(&g_small[threadIdx.x], c[threadIdx.x]);
}

__global__ void count_edges_kernel(const int* __restrict__ src, const int* __restrict__ batch) {
    __shared__ float c[GG];
    if (threadIdx.x < GG) c[threadIdx.x] = 0.f;
    __syncthreads();
    int i = blockIdx.x * blockDim.x + threadIdx.x;
    if (i < EE) atomicAdd(&c[batch[src[i]]], 1.0f);
    __syncthreads();
    if (threadIdx.x < GG && c[threadIdx.x] != 0.f)
        atomicAdd(&g_small[GG + threadIdx.x], c[threadIdx.x]);
}

__global__ void stats_finalize_kernel() {
    if (threadIdx.x != 0 || blockIdx.x != 0) return;
    float lnf[GG], lef[GG];
    for (int g = 0; g < GG; ++g) {
        double nc = (double)fmaxf(g_small[g], 1.0f);
        lnf[g] = (float)log(nc);
        lef[g] = (float)log1p((double)fmaxf(g_small[GG + g], 0.0f));
    }
    double m0 = 0.0, m1 = 0.0;
    for (int g = 0; g < GG; ++g) { m0 += (double)lnf[g]; m1 += (double)lef[g]; }
    m0 /= GG; m1 /= GG;
    double v0 = 0.0, v1 = 0.0;
    float mn = 3.0e38f, mx = -3.0e38f;
    for (int g = 0; g < GG; ++g) {
        double d0 = (double)lnf[g] - m0, d1 = (double)lef[g] - m1;
        v0 += d0 * d0; v1 += d1 * d1;
        mn = fminf(mn, lnf[g]); mx = fmaxf(mx, lnf[g]);
    }
    double s0 = sqrt(v0 / GG), s1 = sqrt(v1 / GG);
    for (int g = 0; g < GG; ++g) {
        g_small[16 + 2 * g + 0] = (float)(((double)lnf[g] - m0) / (s0 + 1e-6));
        g_small[16 + 2 * g + 1] = (float)(((double)lef[g] - m1) / (s1 + 1e-6));
        g_small[32 + g]         = (float)(((double)lnf[g] - (double)mn) /
                                          ((double)mx - (double)mn + 1e-6));
    }
}

// ---------------- CSR build ----------------
__global__ void deg_kernel(const int* __restrict__ dst) {
    int i = blockIdx.x * blockDim.x + threadIdx.x;
    if (i < EE) atomicAdd(&g_deg[dst[i]], 1);
}

__global__ __launch_bounds__(1024) void csr_scan_kernel() {
    __shared__ int tmp[1024];
    int t = threadIdx.x;
    const int CH = (NN + 1023) / 1024;
    int b0 = t * CH;
    int loc = 0;
    for (int i = 0; i < CH; ++i) {
        int idx = b0 + i;
        if (idx < NN) loc += g_deg[idx];
    }
    tmp[t] = loc;
    __syncthreads();
    for (int off = 1; off < 1024; off <<= 1) {
        int v = (t >= off) ? tmp[t - off] : 0;
        __syncthreads();
        tmp[t] += v;
        __syncthreads();
    }
    int run = tmp[t] - loc;
    for (int i = 0; i < CH; ++i) {
        int idx = b0 + i;
        if (idx < NN) {
            g_start[idx] = run;
            g_cursor[idx] = run;
            run += g_deg[idx];
        }
    }
    if (t == 1023) g_start[NN] = tmp[1023];
}

__global__ void csr_scatter_kernel(const int* __restrict__ src, const int* __restrict__ dst) {
    int i = blockIdx.x * blockDim.x + threadIdx.x;
    if (i < EE) {
        int d = dst[i];
        int pos = atomicAdd(&g_cursor[d], 1);
        g_csrc[pos] = src[i];
    }
}

// ---------------- 256-wide gather: planes in -> planes out; 2 nodes/block ----------------
__global__ __launch_bounds__(128) void gather256_kernel(
    const __nv_bfloat16* __restrict__ fhB, const __nv_bfloat16* __restrict__ flB,
    __nv_bfloat16* __restrict__ ohB, __nv_bfloat16* __restrict__ olB) {
    size_t eoff = (size_t)blockIdx.y * ((size_t)NN * HIDD);
    const uint2* fh2 = (const uint2*)(fhB + eoff);
    const uint2* fl2 = (const uint2*)(flB + eoff);
    __nv_bfloat162* oh = (__nv_bfloat162*)(ohB + eoff);
    __nv_bfloat162* ol = (__nv_bfloat162*)(olB + eoff);
    int n = blockIdx.x * 2 + (threadIdx.x >> 6);
    int tid = threadIdx.x & 63;
    if (n >= NN) return;
    int s = g_start[n], e = g_start[n + 1];
    float4 a0 = make_float4(0.f, 0.f, 0.f, 0.f);
    float4 a1 = make_float4(0.f, 0.f, 0.f, 0.f);
    int j = s;
    for (; j + 2 <= e; j += 2) {
        int s0 = __ldg(&g_csrc[j]), s1 = __ldg(&g_csrc[j + 1]);
        uint2 uh0 = fh2[(size_t)s0 * 64 + tid];
        uint2 ul0 = fl2[(size_t)s0 * 64 + tid];
        uint2 uh1 = fh2[(size_t)s1 * 64 + tid];
        uint2 ul1 = fl2[(size_t)s1 * 64 + tid];
        __nv_bfloat162 h00 = *(__nv_bfloat162*)&uh0.x, h01 = *(__nv_bfloat162*)&uh0.y;
        __nv_bfloat162 l00 = *(__nv_bfloat162*)&ul0.x, l01 = *(__nv_bfloat162*)&ul0.y;
        __nv_bfloat162 h10 = *(__nv_bfloat162*)&uh1.x, h11 = *(__nv_bfloat162*)&uh1.y;
        __nv_bfloat162 l10 = *(__nv_bfloat162*)&ul1.x, l11 = *(__nv_bfloat162*)&ul1.y;
        a0.x += __low2float(h00) + __low2float(l00);
        a0.y += __high2float(h00) + __high2float(l00);
        a0.z += __low2float(h01) + __low2float(l01);
        a0.w += __high2float(h01) + __high2float(l01);
        a1.x += __low2float(h10) + __low2float(l10);
        a1.y += __high2float(h10) + __high2float(l10);
        a1.z += __low2float(h11) + __low2float(l11);
        a1.w += __high2float(h11) + __high2float(l11);
    }
    if (j < e) {
        int s0 = __ldg(&g_csrc[j]);
        uint2 uh0 = fh2[(size_t)s0 * 64 + tid];
        uint2 ul0 = fl2[(size_t)s0 * 64 + tid];
        __nv_bfloat162 h00 = *(__nv_bfloat162*)&uh0.x, h01 = *(__nv_bfloat162*)&uh0.y;
        __nv_bfloat162 l00 = *(__nv_bfloat162*)&ul0.x, l01 = *(__nv_bfloat162*)&ul0.y;
        a0.x += __low2float(h00) + __low2float(l00);
        a0.y += __high2float(h00) + __high2float(l00);
        a0.z += __low2float(h01) + __low2float(l01);
        a0.w += __high2float(h01) + __high2float(l01);
    }
    float4 acc = make_float4(a0.x + a1.x, a0.y + a1.y, a0.z + a1.z, a0.w + a1.w);
    __nv_bfloat16 h0 = __float2bfloat16_rn(acc.x);
    __nv_bfloat16 h1 = __float2bfloat16_rn(acc.y);
    __nv_bfloat16 h2 = __float2bfloat16_rn(acc.z);
    __nv_bfloat16 h3 = __float2bfloat16_rn(acc.w);
    size_t base = (size_t)n * 128 + tid * 2;
    oh[base]     = __nv_bfloat162(h0, h1);
    oh[base + 1] = __nv_bfloat162(h2, h3);
    ol[base]     = __nv_bfloat162(__float2bfloat16_rn(acc.x - __bfloat162float(h0)),
                                  __float2bfloat16_rn(acc.y - __bfloat162float(h1)));
    ol[base + 1] = __nv_bfloat162(__float2bfloat16_rn(acc.z - __bfloat162float(h2)),
                                  __float2bfloat16_rn(acc.w - __bfloat162float(h3)));
}

// ---------------- fused encoder: h = relu(x[:,4:10]@w1+b1) @ w2 + b2, + h hi/lo split ----
// A tiles computed in-kernel from x/w1/b1 (exact same FMA order as separate enc1 kernel).
__global__ __launch_bounds__(256) void gemm256_kernel(
    const float* __restrict__ x, const float* __restrict__ w1enc,
    const float* __restrict__ b1enc,
    const float* __restrict__ W1, const float* __restrict__ bias,
    float* __restrict__ C,
    __nv_bfloat162* __restrict__ Chi, __nv_bfloat162* __restrict__ Clo, int M) {
    __shared__ float As[2][16][68];
    __shared__ float Bs[2][16][68];
    __shared__ float sW1[6][256];
    __shared__ float sB1[256];
    int tid = threadIdx.x;
    int ty = tid >> 4, tx = tid & 15;
    int rowBase = blockIdx.x * 64;
    int colBase = blockIdx.y * 64;

    sB1[tid] = b1enc[tid];
    for (int i = tid; i < 1536; i += 256) sW1[i >> 8][i & 255] = w1enc[i];

    float acc[4][4];
#pragma unroll
    for (int i = 0; i < 4; ++i)
#pragma unroll
        for (int j = 0; j < 4; ++j) acc[i][j] = 0.f;

    int aRow = tid >> 2;
    int aCol = (tid & 3) << 2;
    int bRow = tid >> 4;
    int bCol = (tid & 15) << 2;
    int gARow = min(rowBase + aRow, M - 1);

    float xv6[6];
#pragma unroll
    for (int k = 0; k < 6; ++k) xv6[k] = x[(size_t)gARow * 16 + 4 + k];

    float4 bvc = *(const float4*)(W1 + (size_t)(0 + bRow) * 256 + colBase + bCol);
    __syncthreads();  // sW1/sB1 ready

#pragma unroll 1
    for (int t = 0; t < 16; ++t) {
        float (*As_)[68] = As[t & 1];
        float (*Bs_)[68] = Bs[t & 1];
        int kt = t * 16;
        float av[4];
#pragma unroll
        for (int c = 0; c < 4; ++c) {
            int col = kt + aCol + c;
            float v = sB1[col];
#pragma unroll
            for (int k = 0; k < 6; ++k) v += xv6[k] * sW1[k][col];
            av[c] = fmaxf(v, 0.f);
        }
        As_[aCol + 0][aRow] = av[0];
        As_[aCol + 1][aRow] = av[1];
        As_[aCol + 2][aRow] = av[2];
        As_[aCol + 3][aRow] = av[3];
        *(float4*)&Bs_[bRow][bCol] = bvc;
        if (t < 15) {
            int ktn = (t + 1) * 16;
            bvc = *(const float4*)(W1 + (size_t)(ktn + bRow) * 256 + colBase + bCol);
        }
        __syncthreads();
#pragma unroll
        for (int k = 0; k < 16; ++k) {
            float4 a = *(const float4*)&As_[k][ty * 4];
            float4 b = *(const float4*)&Bs_[k][tx * 4];
            acc[0][0] += a.x * b.x; acc[0][1] += a.x * b.y; acc[0][2] += a.x * b.z; acc[0][3] += a.x * b.w;
            acc[1][0] += a.y * b.x; acc[1][1] += a.y * b.y; acc[1][2] += a.y * b.z; acc[1][3] += a.y * b.w;
            acc[2][0] += a.z * b.x; acc[2][1] += a.z * b.y; acc[2][2] += a.z * b.z; acc[2][3] += a.z * b.w;
            acc[3][0] += a.w * b.x; acc[3][1] += a.w * b.y; acc[3][2] += a.w * b.z; acc[3][3] += a.w * b.w;
        }
    }
    int col0 = colBase + tx * 4;
    float4 bv = *(const float4*)(bias + col0);
#pragma unroll
    for (int i = 0; i < 4; ++i) {
        int row = rowBase + ty * 4 + i;
        if (row < M) {
            float4 o;
            o.x = acc[i][0] + bv.x;
            o.y = acc[i][1] + bv.y;
            o.z = acc[i][2] + bv.z;
            o.w = acc[i][3] + bv.w;
            *(float4*)(C + (size_t)row * 256 + col0) = o;
            __nv_bfloat16 h0 = __float2bfloat16_rn(o.x);
            __nv_bfloat16 h1 = __float2bfloat16_rn(o.y);
            __nv_bfloat16 h2 = __float2bfloat16_rn(o.z);
            __nv_bfloat16 h3 = __float2bfloat16_rn(o.w);
            size_t b2i = ((size_t)row * 256 + col0) >> 1;
            Chi[b2i]     = __nv_bfloat162(h0, h1);
            Chi[b2i + 1] = __nv_bfloat162(h2, h3);
            Clo[b2i]     = __nv_bfloat162(__float2bfloat16_rn(o.x - __bfloat162float(h0)),
                                          __float2bfloat16_rn(o.y - __bfloat162float(h1)));
            Clo[b2i + 1] = __nv_bfloat162(__float2bfloat16_rn(o.z - __bfloat162float(h2)),
                                          __float2bfloat16_rn(o.w - __bfloat162float(h3)));
        }
    }
}

// ---------------- weight split+transpose ----------------
__global__ void convert_weights_kernel(const float* __restrict__ w_rel,
                                       const float* __restrict__ w_root) {
    int id = blockIdx.x * blockDim.x + threadIdx.x;
    int slot = id >> 16;
    int r = id & 65535;
    int n = r >> 8, k = r & 255;
    const float* base = (slot < 8) ? (w_rel + (size_t)slot * 65536)
                                   : (w_root + (size_t)(slot - 8) * 65536);
    float v = base[(size_t)k * 256 + n];
    __nv_bfloat16 hi = __float2bfloat16_rn(v);
    float rest = v - __bfloat162float(hi);
    g_wth[(size_t)slot * 65536 + n * 256 + k] = hi;
    g_wtl[(size_t)slot * 65536 + n * 256 + k] = __float2bfloat16_rn(rest);
}

// ---------------- batched tensor-core split-bf16 dual GEMM (64x128, double-buffered) ----
#define MMA_BF16(D, A, B0, B1)                                                        \
    asm volatile(                                                                     \
        "mma.sync.aligned.m16n8k16.row.col.f32.bf16.bf16.f32 "                        \
        "{%0,%1,%2,%3},{%4,%5,%6,%7},{%8,%9},{%0,%1,%2,%3};\n"                        \
        : "+f"((D)[0]), "+f"((D)[1]), "+f"((D)[2]), "+f"((D)[3])                      \
        : "r"((A)[0]), "r"((A)[1]), "r"((A)[2]), "r"((A)[3]), "r"(B0), "r"(B1))

#define SM_BUF   30720
#define SM_AH    0
#define SM_AL    5120
#define SM_WH    10240
#define SM_WL    20480
#define GEMM_SMEM (2 * SM_BUF)

__global__ __launch_bounds__(256) void expert_gemm_kernel(
    const __nv_bfloat16* __restrict__ A1hB, const __nv_bfloat16* __restrict__ A1lB,
    const __nv_bfloat16* __restrict__ A2hB, const __nv_bfloat16* __restrict__ A2lB,
    const __nv_bfloat16* __restrict__ WthB, const __nv_bfloat16* __restrict__ WtlB,
    const float* __restrict__ brel, float* __restrict__ CB,
    __nv_bfloat16* __restrict__ ChiB, __nv_bfloat16* __restrict__ CloB,
    int layer, int M) {
    extern __shared__ char dynsm[];
    int e = blockIdx.z;
    const size_t NH_ = (size_t)NN * HIDD;
    size_t aoff = layer ? (size_t)e * NH_ : 0;
    const __nv_bfloat16* Ah[2] = {A1hB + aoff, A2hB + aoff};
    const __nv_bfloat16* Al[2] = {A1lB + aoff, A2lB + aoff};
    int sRel = e * 2 + layer, sRoot = 8 + e * 2 + layer;
    const __nv_bfloat16* Wh[2] = {WthB + (size_t)sRel * 65536, WthB + (size_t)sRoot * 65536};
    const __nv_bfloat16* Wl[2] = {WtlB + (size_t)sRel * 65536, WtlB + (size_t)sRoot * 65536};
    const float* bias = brel + (size_t)(e * 2 + layer) * 256;
    float* C = CB ? (CB + (size_t)e * NH_) : nullptr;
    __nv_bfloat162* Chi = ChiB ? (__nv_bfloat162*)(ChiB + (size_t)e * NH_) : nullptr;
    __nv_bfloat162* Clo = CloB ? (__nv_bfloat162*)(CloB + (size_t)e * NH_) : nullptr;

    int tid = threadIdx.x;
    int lane = tid & 31, w = tid >> 5;
    int warpM0 = (w & 1) * 32;
    int warpN0 = (w >> 1) * 32;
    int blockM0 = blockIdx.x * 64;
    int blockN0 = blockIdx.y * 128;
    int g = lane >> 2, q = lane & 3;
    int arow = tid >> 2;
    int ak8 = (tid & 3) * 8;
    int gr = min(blockM0 + arow, M - 1);

    float d[2][4][4];
#pragma unroll
    for (int mt = 0; mt < 2; ++mt)
#pragma unroll
        for (int nt = 0; nt < 4; ++nt)
#pragma unroll
            for (int i = 0; i < 4; ++i) d[mt][nt][i] = 0.f;

    float4 cur[6];
    {
        const int kc = 0;
        cur[0] = *(const float4*)(Ah[0] + (size_t)gr * 256 + kc + ak8);
        cur[1] = *(const float4*)(Al[0] + (size_t)gr * 256 + kc + ak8);
        cur[2] = *(const float4*)(Wh[0] + (size_t)(blockN0 + arow) * 256 + kc + ak8);
        cur[3] = *(const float4*)(Wh[0] + (size_t)(blockN0 + arow + 64) * 256 + kc + ak8);
        cur[4] = *(const float4*)(Wl[0] + (size_t)(blockN0 + arow) * 256 + kc + ak8);
        cur[5] = *(const float4*)(Wl[0] + (size_t)(blockN0 + arow + 64) * 256 + kc + ak8);
    }

#pragma unroll 1
    for (int t = 0; t < 16; ++t) {
        char* buf = dynsm + (t & 1) * SM_BUF;
        __nv_bfloat16* bAh = (__nv_bfloat16*)(buf + SM_AH);
        __nv_bfloat16* bAl = (__nv_bfloat16*)(buf + SM_AL);
        __nv_bfloat16* bWh = (__nv_bfloat16*)(buf + SM_WH);
        __nv_bfloat16* bWl = (__nv_bfloat16*)(buf + SM_WL);
        *(float4*)&bAh[arow * 40 + ak8] = cur[0];
        *(float4*)&bAl[arow * 40 + ak8] = cur[1];
        *(float4*)&bWh[arow * 40 + ak8] = cur[2];
        *(float4*)&bWh[(arow + 64) * 40 + ak8] = cur[3];
        *(float4*)&bWl[arow * 40 + ak8] = cur[4];
        *(float4*)&bWl[(arow + 64) * 40 + ak8] = cur[5];
        if (t < 15) {
            int tn = t + 1;
            int pass = tn >> 3, kc = (tn & 7) * 32;
            cur[0] = *(const float4*)(Ah[pass] + (size_t)gr * 256 + kc + ak8);
            cur[1] = *(const float4*)(Al[pass] + (size_t)gr * 256 + kc + ak8);
            cur[2] = *(const float4*)(Wh[pass] + (size_t)(blockN0 + arow) * 256 + kc + ak8);
            cur[3] = *(const float4*)(Wh[pass] + (size_t)(blockN0 + arow + 64) * 256 + kc + ak8);
            cur[4] = *(const float4*)(Wl[pass] + (size_t)(blockN0 + arow) * 256 + kc + ak8);
            cur[5] = *(const float4*)(Wl[pass] + (size_t)(blockN0 + arow + 64) * 256 + kc + ak8);
        }
        __syncthreads();
#pragma unroll
        for (int ks = 0; ks < 32; ks += 16) {
            int k0 = ks + q * 2;
            unsigned ah[2][4], al[2][4];
#pragma unroll
            for (int mt = 0; mt < 2; ++mt) {
                int r = warpM0 + mt * 16 + g;
                ah[mt][0] = *(const unsigned*)&bAh[r * 40 + k0];
                ah[mt][1] = *(const unsigned*)&bAh[(r + 8) * 40 + k0];
                ah[mt][2] = *(const unsigned*)&bAh[r * 40 + k0 + 8];
                ah[mt][3] = *(const unsigned*)&bAh[(r + 8) * 40 + k0 + 8];
                al[mt][0] = *(const unsigned*)&bAl[r * 40 + k0];
                al[mt][1] = *(const unsigned*)&bAl[(r + 8) * 40 + k0];
                al[mt][2] = *(const unsigned*)&bAl[r * 40 + k0 + 8];
                al[mt][3] = *(const unsigned*)&bAl[(r + 8) * 40 + k0 + 8];
            }
#pragma unroll
            for (int nt = 0; nt < 4; ++nt) {
                int n = warpN0 + nt * 8 + g;
                unsigned bh0 = *(const unsigned*)&bWh[n * 40 + k0];
                unsigned bh1 = *(const unsigned*)&bWh[n * 40 + k0 + 8];
                unsigned bl0 = *(const unsigned*)&bWl[n * 40 + k0];
                unsigned bl1 = *(const unsigned*)&bWl[n * 40 + k0 + 8];
#pragma unroll
                for (int mt = 0; mt < 2; ++mt) {
                    MMA_BF16(d[mt][nt], ah[mt], bh0, bh1);
                    MMA_BF16(d[mt][nt], ah[mt], bl0, bl1);
                    MMA_BF16(d[mt][nt], al[mt], bh0, bh1);
                }
            }
        }
    }
#pragma unroll
    for (int mt = 0; mt < 2; ++mt) {
        int r = blockM0 + warpM0 + mt * 16 + g;
#pragma unroll
        for (int nt = 0; nt < 4; ++nt) {
            int col = blockN0 + warpN0 + nt * 8 + q * 2;
            float b0 = bias[col], b1 = bias[col + 1];
#pragma unroll
            for (int half = 0; half < 2; ++half) {
                int rr = r + half * 8;
                if (rr < M) {
                    float ox = fmaxf(d[mt][nt][half * 2 + 0] + b0, 0.f);
                    float oy = fmaxf(d[mt][nt][half * 2 + 1] + b1, 0.f);
                    if (C) *(float2*)(C + (size_t)rr * 256 + col) = make_float2(ox, oy);
                    if (Chi) {
                        __nv_bfloat16 h0 = __float2bfloat16_rn(ox);
                        __nv_bfloat16 h1 = __float2bfloat16_rn(oy);
                        size_t b2i = ((size_t)rr * 256 + col) >> 1;
                        Chi[b2i] = __nv_bfloat162(h0, h1);
                        Clo[b2i] = __nv_bfloat162(
                            __float2bfloat16_rn(ox - __bfloat162float(h0)),
                            __float2bfloat16_rn(oy - __bfloat162float(h1)));
                    }
                }
            }
        }
    }
}

// ---------------- compensated accumulation: TwoProd + Kahan ----------------
__device__ __forceinline__ void kacc(float& s, float& c, float a, float b) {
    float p = __fmul_rn(a, b);
    float e = __fmaf_rn(a, b, -p);
    float y = __fadd_rn(p, -c);
    float t = __fadd_rn(s, y);
    c = __fadd_rn(__fadd_rn(t, -s), -y);
    c = __fadd_rn(c, -e);
    s = t;
}
// final value = s - c

// ---------------- fast router (fp32) + tie flagging ----------------
#define TIE_TAU 1e-3f

__global__ __launch_bounds__(128) void router_fast_kernel(
    const float* __restrict__ h, const int* __restrict__ batch,
    const float* __restrict__ w1, const float* __restrict__ b1,
    const float* __restrict__ lng, const float* __restrict__ lnb,
    const float* __restrict__ w2, const float* __restrict__ b2,
    const float* __restrict__ centers, float* __restrict__ sw) {
    __shared__ float sh[8][260];
    __shared__ float rbuf[8][128];
    __shared__ float smu[8], srs[8], snl[8];
    __shared__ float slog[8][4];
    int node0 = blockIdx.x * 8;
    int tid = threadIdx.x;
    for (int r = 0; r < 8; ++r) {
        int node = node0 + r;
        if (node < NN) {
            for (int k = tid; k < 256; k += 128) sh[r][k] = h[(size_t)node * 256 + k];
            if (tid == 0) {
                int b = batch[node];
                sh[r][256] = g_small[16 + 2 * b + 0];
                sh[r][257] = g_small[16 + 2 * b + 1];
                snl[r] = g_small[32 + b];
            }
        }
    }
    __syncthreads();
    float acc[8];
#pragma unroll
    for (int r = 0; r < 8; ++r) acc[r] = 0.f;
    for (int k = 0; k < 258; ++k) {
        float wv = w1[k * 128 + tid];
#pragma unroll
        for (int r = 0; r < 8; ++r) acc[r] = __fmaf_rn(sh[r][k], wv, acc[r]);
    }
    float bb = b1[tid];
    float rv[8];
#pragma unroll
    for (int r = 0; r < 8; ++r) { rv[r] = acc[r] + bb; rbuf[r][tid] = rv[r]; }
    __syncthreads();
    int wid = tid >> 5, lane = tid & 31;
    for (int rr = 0; rr < 2; ++rr) {
        int r = wid * 2 + rr;
        float a0 = rbuf[r][lane], a1 = rbuf[r][lane + 32], a2 = rbuf[r][lane + 64], a3 = rbuf[r][lane + 96];
        float s = a0 + a1 + a2 + a3;
#pragma unroll
        for (int off = 16; off; off >>= 1) s += __shfl_down_sync(0xffffffffu, s, off);
        float mu = __shfl_sync(0xffffffffu, s, 0) * (1.0f / 128.0f);
        float d0 = a0 - mu, d1 = a1 - mu, d2 = a2 - mu, d3 = a3 - mu;
        float v = d0 * d0 + d1 * d1 + d2 * d2 + d3 * d3;
#pragma unroll
        for (int off = 16; off; off >>= 1) v += __shfl_down_sync(0xffffffffu, v, off);
        if (lane == 0) {
            smu[r] = mu;
            float varf = v * (1.0f / 128.0f) + 1e-5f;
            srs[r] = (float)(1.0 / sqrt((double)varf));
        }
    }
    __syncthreads();
    float gch = lng[tid], bch = lnb[tid];
#pragma unroll
    for (int r = 0; r < 8; ++r) {
        float v = (rv[r] - smu[r]) * srs[r] * gch + bch;
        rbuf[r][tid] = fmaxf(v, 0.f);
    }
    __syncthreads();
    if (tid < 32) {
        int r = tid >> 2, ne = tid & 3;
        float s = 0.f;
        for (int j = 0; j < 128; ++j) s = __fmaf_rn(rbuf[r][j], w2[j * 4 + ne], s);
        float learned = s + b2[ne];
        float d = snl[r] - centers[ne];
        slog[r][ne] = 0.65f * learned - 0.35f * d * d;
    }
    __syncthreads();
    if (tid < 8) {
        int node = node0 + tid;
        if (node < NN) {
            float lg[4];
#pragma unroll
            for (int ne = 0; ne < 4; ++ne) lg[ne] = slog[tid][ne];
            int i1 = 0;
#pragma unroll
            for (int ne = 1; ne < 4; ++ne) if (lg[ne] > lg[i1]) i1 = ne;
            int i2 = -1;
#pragma unroll
            for (int ne = 0; ne < 4; ++ne) if (ne != i1 && (i2 < 0 || lg[ne] > lg[i2])) i2 = ne;
            int i3 = -1;
#pragma unroll
            for (int ne = 0; ne < 4; ++ne) if (ne != i1 && ne != i2 && (i3 < 0 || lg[ne] > lg[i3])) i3 = ne;
            float mx = lg[i1];
            float p[4], sum = 0.f;
#pragma unroll
            for (int ne = 0; ne < 4; ++ne) { p[ne] = __expf(lg[ne] - mx); sum += p[ne]; }
            float inv = 1.0f / sum;
            float v1 = p[i1] * inv, v2 = p[i2] * inv;
            float norm = 1.0f / (v1 + v2 + 1e-8f);
            float o[4] = {0.f, 0.f, 0.f, 0.f};
            o[i1] = v1 * norm; o[i2] = v2 * norm;
#pragma unroll
            for (int ne = 0; ne < 4; ++ne) sw[(size_t)node * 4 + ne] = o[ne];
            if (lg[i2] - lg[i3] < TIE_TAU) {
                int pos = atomicAdd(&g_nflag, 1);
                g_flag[pos] = node;
            }
        }
    }
}

// ---------------- exact router fixup for flagged (near-tie) nodes ----------------
__global__ __launch_bounds__(128) void router_fix_kernel(
    const float* __restrict__ h, const int* __restrict__ batch,
    const float* __restrict__ w1, const float* __restrict__ b1,
    const float* __restrict__ lng, const float* __restrict__ lnb,
    const float* __restrict__ w2, const float* __restrict__ b2,
    const float* __restrict__ centers, float* __restrict__ sw) {
    __shared__ float sh[260];
    __shared__ float rbuf[128];
    __shared__ float red[8];
    __shared__ float snl1;
    __shared__ double slogd[4];
    int tid = threadIdx.x;
    int wid = tid >> 5, lane = tid & 31;
    int nflag = g_nflag;
    for (int fi = blockIdx.x; fi < nflag; fi += gridDim.x) {
        int node = g_flag[fi];
        for (int k = tid; k < 256; k += 128) sh[k] = h[(size_t)node * 256 + k];
        if (tid == 0) {
            int b = batch[node];
            sh[256] = g_small[16 + 2 * b + 0];
            sh[257] = g_small[16 + 2 * b + 1];
            snl1 = g_small[32 + b];
        }
        __syncthreads();
        float s = 0.f, c = 0.f;
        for (int k = 0; k < 258; ++k) kacc(s, c, sh[k], w1[k * 128 + tid]);
        float rv = (s - c) + b1[tid];
        float v = rv;
#pragma unroll
        for (int off = 16; off; off >>= 1) v += __shfl_down_sync(0xffffffffu, v, off);
        if (lane == 0) red[wid] = v;
        __syncthreads();
        float mu = (red[0] + red[1] + red[2] + red[3]) * (1.0f / 128.0f);
        float dd = rv - mu;
        float vv = dd * dd;
#pragma unroll
        for (int off = 16; off; off >>= 1) vv += __shfl_down_sync(0xffffffffu, vv, off);
        if (lane == 0) red[4 + wid] = vv;
        __syncthreads();
        float var = (red[4] + red[5] + red[6] + red[7]) * (1.0f / 128.0f) + 1e-5f;
        float rs = (float)(1.0 / sqrt((double)var));
        rbuf[tid] = fmaxf((rv - mu) * rs * lng[tid] + lnb[tid], 0.f);
        __syncthreads();
        if (tid < 4) {
            float ss = 0.f, cc = 0.f;
            for (int j = 0; j < 128; ++j) kacc(ss, cc, rbuf[j], w2[j * 4 + tid]);
            float learned = (ss - cc) + b2[tid];
            double d = (double)snl1 - (double)centers[tid];
            slogd[tid] = 0.65 * (double)learned - 0.35 * d * d;
        }
        __syncthreads();
        if (tid == 0) {
            double lg[4];
#pragma unroll
            for (int ne = 0; ne < 4; ++ne) lg[ne] = slogd[ne];
            double mx = lg[0];
#pragma unroll
            for (int ne = 1; ne < 4; ++ne) mx = fmax(mx, lg[ne]);
            double pd[4], sum = 0.0;
#pragma unroll
            for (int ne = 0; ne < 4; ++ne) { pd[ne] = exp(lg[ne] - mx); sum += pd[ne]; }
            float p[4];
#pragma unroll
            for (int ne = 0; ne < 4; ++ne) p[ne] = (float)(pd[ne] / sum);
            int i1 = 0;
#pragma unroll
            for (int ne = 1; ne < 4; ++ne) if (lg[ne] > lg[i1]) i1 = ne;
            int i2 = -1;
#pragma unroll
            for (int ne = 0; ne < 4; ++ne) if (ne != i1 && (i2 < 0 || lg[ne] > lg[i2])) i2 = ne;
            float v1 = p[i1], v2 = p[i2];
            float norm = 1.0f / (v1 + v2 + 1e-8f);
            float o[4] = {0.f, 0.f, 0.f, 0.f};
            o[i1] = v1 * norm; o[i2] = v2 * norm;
#pragma unroll
            for (int ne = 0; ne < 4; ++ne) sw[(size_t)node * 4 + ne] = o[ne];
        }
        __syncthreads();
    }
}

// ---------------- vu projection (batched over experts via blockIdx.y) ----------------
__global__ __launch_bounds__(256) void vu_kernel(
    const float* __restrict__ xe2B,
    const float* __restrict__ wroB,
    const float* __restrict__ wrtB,
    float* __restrict__ vbuf,
    float* __restrict__ ubuf) {
    __shared__ float sWv[8][260];
    __shared__ float sWu[8][260];
    int e = blockIdx.y;
    const float* xe2 = xe2B + (size_t)e * NN * HIDD;
    const float* wro = wroB + (size_t)e * 1536;
    const float* wrt = wrtB + (size_t)e * 1536;
    int t = threadIdx.x;
    for (int i = t; i < 1536; i += 256) {
        int k = i / 6, j = i % 6;
        sWv[j][k] = wro[i];
        sWu[j][k] = wrt[i];
    }
    __syncthreads();
    int nloc = t >> 3, j = t & 7;
    int n = blockIdx.x * 32 + nloc;
    if (n >= NN) return;
    float v = 0.f, u = 0.f;
    if (j < 6) {
        const float4* xr = (const float4*)(xe2 + (size_t)n * 256);
#pragma unroll 4
        for (int k4 = 0; k4 < 64; ++k4) {
            float4 xv = xr[k4];
            int k = k4 * 4;
            v += xv.x * sWv[j][k] + xv.y * sWv[j][k + 1] + xv.z * sWv[j][k + 2] + xv.w * sWv[j][k + 3];
            u += xv.x * sWu[j][k] + xv.y * sWu[j][k + 1] + xv.z * sWu[j][k + 2] + xv.w * sWu[j][k + 3];
        }
    }
    vbuf[(size_t)n * 32 + e * 8 + j] = v;
    ubuf[(size_t)n * 32 + e * 8 + j] = u;
}

// ---------------- final output ----------------
__global__ __launch_bounds__(256) void out_final_kernel(
    const float* __restrict__ vbuf, const float* __restrict__ ubuf,
    const float* __restrict__ sw, const float* __restrict__ bro,
    float* __restrict__ out) {
    int warp = (blockIdx.x * 256 + threadIdx.x) >> 5;
    int lane = threadIdx.x & 31;
    if (warp >= NN) return;
    int e = lane >> 3, j = lane & 7;
    int s = g_start[warp], en = g_start[warp + 1];
    float sum0 = 0.f, sum1 = 0.f;
    int jj = s;
    for (; jj + 2 <= en; jj += 2) {
        int s0 = __ldg(&g_csrc[jj]), s1 = __ldg(&g_csrc[jj + 1]);
        sum0 += vbuf[(size_t)s0 * 32 + lane];
        sum1 += vbuf[(size_t)s1 * 32 + lane];
    }
    if (jj < en) sum0 += vbuf[(size_t)__ldg(&g_csrc[jj]) * 32 + lane];
    float sum = sum0 + sum1;
    float u = ubuf[(size_t)warp * 32 + lane];
    float bj = (j < 6) ? bro[e * 6 + j] : 0.f;
    float swv = sw[(size_t)warp * 4 + e];
    float val = swv * (sum + u + bj);
    val += __shfl_down_sync(0xffffffffu, val, 16);
    val += __shfl_down_sync(0xffffffffu, val, 8);
    if (lane < 6) out[(size_t)warp * 6 + lane] = val;
}

// ---------------- host launch ----------------
extern "C" void kernel_launch(void* const* d_in, const int* in_sizes, int n_in,
                              void* d_out, int out_size) {
    const float* x       = (const float*)d_in[0];
    const int*   ei      = (const int*)d_in[1];
    const int*   batch   = (const int*)d_in[2];
    const float* enc_w1  = (const float*)d_in[4];
    const float* enc_b1  = (const float*)d_in[5];
    const float* enc_w2  = (const float*)d_in[6];
    const float* enc_b2  = (const float*)d_in[7];
    const float* rt_w1   = (const float*)d_in[8];
    const float* rt_b1   = (const float*)d_in[9];
    const float* ln_g    = (const float*)d_in[10];
    const float* ln_b    = (const float*)d_in[11];
    const float* rt_w2   = (const float*)d_in[12];
    const float* rt_b2   = (const float*)d_in[13];
    const float* centers = (const float*)d_in[14];
    const float* w_rel   = (const float*)d_in[15];
    const float* b_rel   = (const float*)d_in[16];
    const float* w_root  = (const float*)d_in[17];
    const float* w_rout  = (const float*)d_in[18];
    const float* b_rout  = (const float*)d_in[19];
    const float* w_rtout = (const float*)d_in[20];
    float* out = (float*)d_out;

    static float *ph = nullptr, *psw, *psmall, *pxe2f, *pvbuf, *pubuf;
    static __nv_bfloat16 *p0h, *p0l, *p1h, *p1l, *pxeh, *pxel, *pagh, *pagl, *pwh, *pwl;
    static int* pdeg;
    static cudaStream_t sB = nullptr, sC = nullptr;
    static cudaEvent_t evRoot, evStats, evW, evH, evAggh, evRouter;
    static cudaEvent_t evL1, evG, evL2, evVU;
    if (!ph) {
        cudaGetSymbolAddress((void**)&ph,     g_h);
        cudaGetSymbolAddress((void**)&psw,    g_sw);
        cudaGetSymbolAddress((void**)&psmall, g_small);
        cudaGetSymbolAddress((void**)&p0h, g_p0h);
        cudaGetSymbolAddress((void**)&p0l, g_p0l);
        cudaGetSymbolAddress((void**)&p1h, g_p1h);
        cudaGetSymbolAddress((void**)&p1l, g_p1l);
        cudaGetSymbolAddress((void**)&pxeh, g_xeh);
        cudaGetSymbolAddress((void**)&pxel, g_xel);
        cudaGetSymbolAddress((void**)&pagh, g_agh);
        cudaGetSymbolAddress((void**)&pagl, g_agl);
        cudaGetSymbolAddress((void**)&pxe2f, g_xe2f);
        cudaGetSymbolAddress((void**)&pvbuf, g_vbuf);
        cudaGetSymbolAddress((void**)&pubuf, g_ubuf);
        cudaGetSymbolAddress((void**)&pwh, g_wth);
        cudaGetSymbolAddress((void**)&pwl, g_wtl);
        cudaGetSymbolAddress((void**)&pdeg, g_deg);
        cudaFuncSetAttribute(expert_gemm_kernel,
                             cudaFuncAttributeMaxDynamicSharedMemorySize, GEMM_SMEM);
        cudaStreamCreateWithFlags(&sB, cudaStreamNonBlocking);
        cudaStreamCreateWithFlags(&sC, cudaStreamNonBlocking);
        cudaEventCreateWithFlags(&evRoot,   cudaEventDisableTiming);
        cudaEventCreateWithFlags(&evStats,  cudaEventDisableTiming);
        cudaEventCreateWithFlags(&evW,      cudaEventDisableTiming);
        cudaEventCreateWithFlags(&evH,      cudaEventDisableTiming);
        cudaEventCreateWithFlags(&evAggh,   cudaEventDisableTiming);
        cudaEventCreateWithFlags(&evRouter, cudaEventDisableTiming);
        cudaEventCreateWithFlags(&evL1, cudaEventDisableTiming);
        cudaEventCreateWithFlags(&evG,  cudaEventDisableTiming);
        cudaEventCreateWithFlags(&evL2, cudaEventDisableTiming);
        cudaEventCreateWithFlags(&evVU, cudaEventDisableTiming);
    }

    const int* src = ei;
    const int* dst = ei + EE;

    // fork
    cudaEventRecord(evRoot, 0);
    cudaStreamWaitEvent(sB, evRoot, 0);
    cudaStreamWaitEvent(sC, evRoot, 0);

    // ---- stream A (default): fused encoder ----
    dim3 ggrid((NN + 63) / 64, 4);
    gemm256_kernel<<<ggrid, 256>>>(x, enc_w1, enc_b1, enc_w2, enc_b2, ph,
                                   (__nv_bfloat162*)p1h, (__nv_bfloat162*)p1l, NN);
    cudaEventRecord(evH, 0);

    // ---- stream B: stats + CSR + weight split ----
    zero_kernel<<<1, 32, 0, sB>>>(psmall, 64);
    zero_kernel<<<(NN / 4 + 255) / 256, 256, 0, sB>>>((float*)pdeg, NN);
    count_nodes_kernel<<<(NN + 255) / 256, 256, 0, sB>>>(batch);
    count_edges_kernel<<<(EE + 255) / 256, 256, 0, sB>>>(src, batch);
    stats_finalize_kernel<<<1, 32, 0, sB>>>();
    cudaEventRecord(evStats, sB);
    deg_kernel<<<(EE + 255) / 256, 256, 0, sB>>>(dst);
    csr_scan_kernel<<<1, 1024, 0, sB>>>();
    csr_scatter_kernel<<<(EE + 255) / 256, 256, 0, sB>>>(src, dst);
    convert_weights_kernel<<<(16 * 65536) / 256, 256, 0, sB>>>(w_rel, w_root);
    cudaEventRecord(evW, sB);

    // ---- stream C: two-pass router ----
    cudaStreamWaitEvent(sC, evStats, 0);
    cudaStreamWaitEvent(sC, evH, 0);
    zero_nflag_kernel<<<1, 32, 0, sC>>>();
    router_fast_kernel<<<(NN + 7) / 8, 128, 0, sC>>>(ph, batch, rt_w1, rt_b1, ln_g, ln_b,
                                                     rt_w2, rt_b2, centers, psw);
    router_fix_kernel<<<64, 128, 0, sC>>>(ph, batch, rt_w1, rt_b1, ln_g, ln_b,
                                          rt_w2, rt_b2, centers, psw);
    cudaEventRecord(evRouter, sC);

    // ---- B: aggh gather (h planes -> aggh planes) ----
    cudaStreamWaitEvent(sB, evH, 0);
    gather256_kernel<<<dim3((NN + 1) / 2, 1), 128, 0, sB>>>(p1h, p1l, p0h, p0l);
    cudaEventRecord(evAggh, sB);

    // ---- A: batched expert L1 GEMM (z = expert) ----
    cudaStreamWaitEvent(0, evW, 0);
    cudaStreamWaitEvent(0, evAggh, 0);
    dim3 tcgrid((NN + 63) / 64, 2, NEXP);
    expert_gemm_kernel<<<tcgrid, 256, GEMM_SMEM>>>(p0h, p0l, p1h, p1l, pwh, pwl,
                                                   b_rel, nullptr, pxeh, pxel, 0, NN);
    cudaEventRecord(evL1, 0);

    // ---- B: batched xe gathers (y = expert) ----
    cudaStreamWaitEvent(sB, evL1, 0);
    gather256_kernel<<<dim3((NN + 1) / 2, NEXP), 128, 0, sB>>>(pxeh, pxel, pagh, pagl);
    cudaEventRecord(evG, sB);

    // ---- A: batched expert L2 GEMM ----
    cudaStreamWaitEvent(0, evG, 0);
    expert_gemm_kernel<<<tcgrid, 256, GEMM_SMEM>>>(pagh, pagl, pxeh, pxel, pwh, pwl,
                                                   b_rel, pxe2f, nullptr, nullptr, 1, NN);
    cudaEventRecord(evL2, 0);

    // ---- B: batched vu projections ----
    cudaStreamWaitEvent(sB, evL2, 0);
    vu_kernel<<<dim3((NN + 31) / 32, NEXP), 256, 0, sB>>>(pxe2f, w_rout, w_rtout,
                                                          pvbuf, pubuf);
    cudaEventRecord(evVU, sB);

    // ---- A: final output ----
    cudaStreamWaitEvent(0, evRouter, 0);
    cudaStreamWaitEvent(0, evVU, 0);
    out_final_kernel<<<(NN * 32 + 255) / 256, 256>>>(pvbuf, pubuf, psw, b_rout, out);
}